// round 1
// baseline (speedup 1.0000x reference)
#include <cuda_runtime.h>
#include <cuda_bf16.h>
#include <math.h>

// Problem constants (fixed by the reference)
#define Bb 8
#define Tt 2048
#define Ee 2048
#define FFF 8192
#define MR (Bb * Tt)   // 16384 rows total

// ---------------- scratch (static device globals; zero-init .bss) ----------
__device__ float g_h   [(size_t)MR * Ee];   // LN output (reused for LN2)
__device__ float g_q   [(size_t)MR * Ee];
__device__ float g_k   [(size_t)MR * Ee];
__device__ float g_v   [(size_t)MR * Ee];
__device__ float g_s   [(size_t)Bb * Tt * Tt];  // attention scores / probs
__device__ float g_attn[(size_t)MR * Ee];
__device__ float g_x1  [(size_t)MR * Ee];   // x + attn residual
__device__ float g_ff  [(size_t)MR * FFF];  // FF hidden

// ---------------- LayerNorm: one block per row of E=2048 -------------------
__global__ void ln_kernel(const float* __restrict__ x,
                          const float* __restrict__ gamma,
                          const float* __restrict__ beta,
                          float* __restrict__ out)
{
    int row = blockIdx.x;
    const float* xr = x + (size_t)row * Ee;
    float* orow = out + (size_t)row * Ee;

    float s = 0.f, s2 = 0.f;
    for (int i = threadIdx.x; i < Ee; i += 256) {
        float v = xr[i];
        s += v; s2 += v * v;
    }
    __shared__ float sh[64];
    #pragma unroll
    for (int off = 16; off; off >>= 1) {
        s  += __shfl_xor_sync(0xffffffffu, s,  off);
        s2 += __shfl_xor_sync(0xffffffffu, s2, off);
    }
    int w = threadIdx.x >> 5, lane = threadIdx.x & 31;
    if (lane == 0) { sh[w] = s; sh[32 + w] = s2; }
    __syncthreads();
    if (w == 0) {
        s  = (lane < 8) ? sh[lane]      : 0.f;
        s2 = (lane < 8) ? sh[32 + lane] : 0.f;
        #pragma unroll
        for (int off = 4; off; off >>= 1) {
            s  += __shfl_xor_sync(0xffffffffu, s,  off);
            s2 += __shfl_xor_sync(0xffffffffu, s2, off);
        }
        if (lane == 0) { sh[0] = s; sh[1] = s2; }
    }
    __syncthreads();
    float mean = sh[0] * (1.f / Ee);
    float var  = sh[1] * (1.f / Ee) - mean * mean;
    float inv  = rsqrtf(var + 1e-5f);
    for (int i = threadIdx.x; i < Ee; i += 256)
        orow[i] = (xr[i] - mean) * inv * gamma[i] + beta[i];
}

// ---------------- Causal softmax over scores rows --------------------------
// Row (b, t): softmax over s in [0, t] of raw/sqrt(E); zero-fill s in (t, T).
__global__ void softmax_kernel(float* __restrict__ S)
{
    int t = blockIdx.x, b = blockIdx.y;
    float* row = S + ((size_t)b * Tt + t) * Tt;
    int n = t + 1;
    const float scale = 0.0220970869120796101f;  // 1/sqrt(2048)

    __shared__ float sh[32];
    int w = threadIdx.x >> 5, lane = threadIdx.x & 31;

    // max
    float mx = -3.4e38f;
    for (int i = threadIdx.x; i < n; i += 256) mx = fmaxf(mx, row[i]);
    #pragma unroll
    for (int off = 16; off; off >>= 1) mx = fmaxf(mx, __shfl_xor_sync(0xffffffffu, mx, off));
    if (lane == 0) sh[w] = mx;
    __syncthreads();
    if (w == 0) {
        mx = (lane < 8) ? sh[lane] : -3.4e38f;
        #pragma unroll
        for (int off = 4; off; off >>= 1) mx = fmaxf(mx, __shfl_xor_sync(0xffffffffu, mx, off));
        if (lane == 0) sh[0] = mx;
    }
    __syncthreads();
    mx = sh[0];
    __syncthreads();

    // sum of exp
    float sum = 0.f;
    for (int i = threadIdx.x; i < n; i += 256) sum += __expf((row[i] - mx) * scale);
    #pragma unroll
    for (int off = 16; off; off >>= 1) sum += __shfl_xor_sync(0xffffffffu, sum, off);
    if (lane == 0) sh[w] = sum;
    __syncthreads();
    if (w == 0) {
        sum = (lane < 8) ? sh[lane] : 0.f;
        #pragma unroll
        for (int off = 4; off; off >>= 1) sum += __shfl_xor_sync(0xffffffffu, sum, off);
        if (lane == 0) sh[0] = sum;
    }
    __syncthreads();
    float inv = 1.f / sh[0];

    for (int i = threadIdx.x; i < Tt; i += 256)
        row[i] = (i < n) ? __expf((row[i] - mx) * scale) * inv : 0.f;
}

// ---------------- Generic tiled fp32 GEMM ----------------------------------
// C[M,N] (row-major) = A[M,K] (row-major) * B
//   NT=true : B is [N,K] row-major (weight layout)      -> C = A * B^T
//   NT=false: B is [K,N] row-major (activation layout)  -> C = A * B
// Optional bias[N], residual res[M,N], ReLU.
// causal: NT  -> skip blocks with n0 > m0+BM-1 (upper triangle)
//         !NT -> limit K loop to m0+BM (PV with zero-filled probs above diag)
// Batched via blockIdx.z with element strides strA/strB/strC.
#define GBM 128
#define GBN 128
#define GBK 8

template<bool RELU, bool NT>
__global__ void __launch_bounds__(256) gemm_kernel(
    const float* __restrict__ A, const float* __restrict__ Bm,
    const float* __restrict__ bias, const float* __restrict__ res,
    float* __restrict__ C, int N, int K,
    size_t strA, size_t strB, size_t strC, int causal)
{
    int m0 = blockIdx.y * GBM;
    int n0 = blockIdx.x * GBN;
    if (causal && NT && n0 > m0 + GBM - 1) return;

    int bz = blockIdx.z;
    A  += (size_t)bz * strA;
    Bm += (size_t)bz * strB;
    C  += (size_t)bz * strC;

    __shared__ float sA[GBK][GBM];
    __shared__ float sB[GBK][GBN];

    int tid = threadIdx.x;
    int tx = tid & 15;        // 0..15 -> 8 cols each
    int ty = tid >> 4;        // 0..15 -> 8 rows each

    float acc[8][8];
    #pragma unroll
    for (int i = 0; i < 8; i++)
        #pragma unroll
        for (int j = 0; j < 8; j++) acc[i][j] = 0.f;

    int kend = K;
    if (causal && !NT) { int lim = m0 + GBM; kend = (lim < K) ? lim : K; }

    // A-tile load indices (also B-tile for NT)
    int lr = tid >> 1;              // 0..127 row within tile
    int lc = (tid & 1) * 4;         // 0 or 4 within BK

    for (int k0 = 0; k0 < kend; k0 += GBK) {
        float4 av = *(const float4*)(A + (size_t)(m0 + lr) * K + k0 + lc);
        float4 bv;
        if (NT) {
            bv = *(const float4*)(Bm + (size_t)(n0 + lr) * K + k0 + lc);
        } else {
            int kr = tid >> 5;            // 0..7
            int nc = (tid & 31) * 4;      // 0..124
            bv = *(const float4*)(Bm + (size_t)(k0 + kr) * N + n0 + nc);
        }
        __syncthreads();
        sA[lc + 0][lr] = av.x; sA[lc + 1][lr] = av.y;
        sA[lc + 2][lr] = av.z; sA[lc + 3][lr] = av.w;
        if (NT) {
            sB[lc + 0][lr] = bv.x; sB[lc + 1][lr] = bv.y;
            sB[lc + 2][lr] = bv.z; sB[lc + 3][lr] = bv.w;
        } else {
            int kr = tid >> 5;
            int nc = (tid & 31) * 4;
            sB[kr][nc + 0] = bv.x; sB[kr][nc + 1] = bv.y;
            sB[kr][nc + 2] = bv.z; sB[kr][nc + 3] = bv.w;
        }
        __syncthreads();

        #pragma unroll
        for (int kk = 0; kk < GBK; kk++) {
            float a[8], b[8];
            #pragma unroll
            for (int i = 0; i < 8; i++) a[i] = sA[kk][ty * 8 + i];
            #pragma unroll
            for (int j = 0; j < 8; j++) b[j] = sB[kk][tx * 8 + j];
            #pragma unroll
            for (int i = 0; i < 8; i++)
                #pragma unroll
                for (int j = 0; j < 8; j++)
                    acc[i][j] = fmaf(a[i], b[j], acc[i][j]);
        }
    }

    // epilogue
    #pragma unroll
    for (int i = 0; i < 8; i++) {
        int m = m0 + ty * 8 + i;
        float* crow = C + (size_t)m * N + n0 + tx * 8;
        const float* rrow = res ? (res + (size_t)m * N + n0 + tx * 8) : nullptr;
        #pragma unroll
        for (int j = 0; j < 8; j++) {
            float v = acc[i][j];
            if (bias) v += __ldg(&bias[n0 + tx * 8 + j]);
            if (rrow) v += rrow[j];
            if (RELU) v = fmaxf(v, 0.f);
            crow[j] = v;
        }
    }
}

// ---------------- launch ----------------------------------------------------
extern "C" void kernel_launch(void* const* d_in, const int* in_sizes, int n_in,
                              void* d_out, int out_size)
{
    const float* x      = (const float*)d_in[0];
    const float* gamma1 = (const float*)d_in[1];
    const float* beta1  = (const float*)d_in[2];
    const float* Wq     = (const float*)d_in[3];
    const float* Wk     = (const float*)d_in[4];
    const float* Wv     = (const float*)d_in[5];
    const float* Wo     = (const float*)d_in[6];
    const float* bo     = (const float*)d_in[7];
    const float* gamma2 = (const float*)d_in[8];
    const float* beta2  = (const float*)d_in[9];
    const float* W1     = (const float*)d_in[10];
    const float* b1     = (const float*)d_in[11];
    const float* W2     = (const float*)d_in[12];
    const float* b2     = (const float*)d_in[13];
    float* out = (float*)d_out;

    float *h, *q, *k, *v, *s, *attn, *x1, *ff;
    cudaGetSymbolAddress((void**)&h,    g_h);
    cudaGetSymbolAddress((void**)&q,    g_q);
    cudaGetSymbolAddress((void**)&k,    g_k);
    cudaGetSymbolAddress((void**)&v,    g_v);
    cudaGetSymbolAddress((void**)&s,    g_s);
    cudaGetSymbolAddress((void**)&attn, g_attn);
    cudaGetSymbolAddress((void**)&x1,   g_x1);
    cudaGetSymbolAddress((void**)&ff,   g_ff);

    // 1) LN1
    ln_kernel<<<MR, 256>>>(x, gamma1, beta1, h);

    // 2) QKV projections: [MR,E] x [E,E]^T
    dim3 gProj(Ee / GBN, MR / GBM, 1);
    gemm_kernel<false, true><<<gProj, 256>>>(h, Wq, nullptr, nullptr, q, Ee, Ee, 0, 0, 0, 0);
    gemm_kernel<false, true><<<gProj, 256>>>(h, Wk, nullptr, nullptr, k, Ee, Ee, 0, 0, 0, 0);
    gemm_kernel<false, true><<<gProj, 256>>>(h, Wv, nullptr, nullptr, v, Ee, Ee, 0, 0, 0, 0);

    // 3) scores S = q k^T (batched over B, causal tile skip)
    dim3 gQK(Tt / GBN, Tt / GBM, Bb);
    gemm_kernel<false, true><<<gQK, 256>>>(q, k, nullptr, nullptr, s, Tt, Ee,
                                           (size_t)Tt * Ee, (size_t)Tt * Ee,
                                           (size_t)Tt * Tt, 1);

    // 4) causal softmax (scaled by 1/sqrt(E)), zero-fills s>t
    softmax_kernel<<<dim3(Tt, Bb), 256>>>(s);

    // 5) attn = S @ V (batched, K-loop limited by causality)
    dim3 gPV(Ee / GBN, Tt / GBM, Bb);
    gemm_kernel<false, false><<<gPV, 256>>>(s, v, nullptr, nullptr, attn, Ee, Tt,
                                            (size_t)Tt * Tt, (size_t)Tt * Ee,
                                            (size_t)Tt * Ee, 1);

    // 6) output projection + bias + residual(x)  -> x1
    gemm_kernel<false, true><<<gProj, 256>>>(attn, Wo, bo, x, x1, Ee, Ee, 0, 0, 0, 0);

    // 7) LN2
    ln_kernel<<<MR, 256>>>(x1, gamma2, beta2, h);

    // 8) FF1 + bias + ReLU: [MR,E] x [FF,E]^T
    dim3 gFF1(FFF / GBN, MR / GBM, 1);
    gemm_kernel<true, true><<<gFF1, 256>>>(h, W1, b1, nullptr, ff, FFF, Ee, 0, 0, 0, 0);

    // 9) FF2 + bias + residual(x1) -> out
    dim3 gFF2(Ee / GBN, MR / GBM, 1);
    gemm_kernel<false, true><<<gFF2, 256>>>(ff, W2, b2, x1, out, Ee, FFF, 0, 0, 0, 0);
}

// round 3
// speedup vs baseline: 2.9235x; 2.9235x over previous
#include <cuda_runtime.h>
#include <cuda_fp16.h>
#include <cstdint>
#include <math.h>

// Problem constants
#define Bb 8
#define Tt 2048
#define Ee 2048
#define FFF 8192
#define MR (Bb * Tt)   // 16384

// ---------------- scratch ---------------------------------------------------
__device__ float g_h   [(size_t)MR * Ee];
__device__ float g_q   [(size_t)MR * Ee];
__device__ float g_k   [(size_t)MR * Ee];
__device__ float g_v   [(size_t)MR * Ee];
__device__ float g_s   [(size_t)Bb * Tt * Tt];
__device__ float g_attn[(size_t)MR * Ee];
__device__ float g_x1  [(size_t)MR * Ee];
__device__ float g_ff  [(size_t)MR * FFF];

// ---------------- helpers ----------------------------------------------------
__device__ __forceinline__ uint32_t smem_u32(const void* p) {
    uint32_t a;
    asm("{ .reg .u64 t; cvta.to.shared.u64 t, %1; cvt.u32.u64 %0, t; }" : "=r"(a) : "l"(p));
    return a;
}

#define LDSM4(r0, r1, r2, r3, a)                                                \
    asm volatile("ldmatrix.sync.aligned.m8n8.x4.shared.b16 {%0,%1,%2,%3}, [%4];"\
        : "=r"(r0), "=r"(r1), "=r"(r2), "=r"(r3) : "r"(a))
#define LDSM4T(r0, r1, r2, r3, a)                                               \
    asm volatile("ldmatrix.sync.aligned.m8n8.x4.trans.shared.b16 {%0,%1,%2,%3}, [%4];"\
        : "=r"(r0), "=r"(r1), "=r"(r2), "=r"(r3) : "r"(a))
#define MMA16816(d, a, b)                                                       \
    asm volatile("mma.sync.aligned.m16n8k16.row.col.f32.f16.f16.f32 "           \
        "{%0,%1,%2,%3}, {%4,%5,%6,%7}, {%8,%9}, {%0,%1,%2,%3};"                 \
        : "+f"((d)[0]), "+f"((d)[1]), "+f"((d)[2]), "+f"((d)[3])                \
        : "r"((a)[0]), "r"((a)[1]), "r"((a)[2]), "r"((a)[3]),                   \
          "r"((b)[0]), "r"((b)[1]))

// fp32 -> (hi fp16, lo fp16) split packs of 2
__device__ __forceinline__ void cvtp(float a, float b, uint32_t& h, uint32_t& l) {
    __half2 hh = __floats2half2_rn(a, b);
    float2 hf = __half22float2(hh);
    __half2 ll = __floats2half2_rn(a - hf.x, b - hf.y);
    h = *reinterpret_cast<uint32_t*>(&hh);
    l = *reinterpret_cast<uint32_t*>(&ll);
}

// ---------------- split-fp16 HMMA GEMM ---------------------------------------
// C[M,N] = A[M,K] * op(B). NN=false: B[N,K] row-major (NT, weights/QK).
// NN=true: B[K,N] row-major (PV). Split fp16 3-term for fp32-like accuracy.
// causal: 1 = skip tiles above diagonal (QK^T), 2 = clamp K at diagonal (PV).
// smem per stage: Ahi(10240) Alo(10240) Bhi(10240) Blo(10240) = 40960 B; 2 stages.
#define HSMEM 81920

template<bool NN, bool RELU>
__global__ void __launch_bounds__(256) hgemm(
    const float* __restrict__ A, const float* __restrict__ B,
    const float* __restrict__ bias, const float* __restrict__ res,
    float* __restrict__ C, int N, int K,
    size_t sA, size_t sB, size_t sC, int causal)
{
    int m0 = blockIdx.y * 128, n0 = blockIdx.x * 128;
    if (causal == 1 && n0 > m0) return;
    A += (size_t)blockIdx.z * sA;
    B += (size_t)blockIdx.z * sB;
    C += (size_t)blockIdx.z * sC;

    extern __shared__ char sm[];
    uint32_t sb = smem_u32(sm);
    int tid = threadIdx.x, lane = tid & 31, wid = tid >> 5;
    int wm = (wid & 3) * 32, wn = (wid >> 2) * 64;

    int kend = K;
    if (causal == 2) { int l = m0 + 128; kend = (l < K) ? l : K; }
    int nch = kend >> 5;

    float c[2][8][4];
    #pragma unroll
    for (int i = 0; i < 2; i++)
        #pragma unroll
        for (int j = 0; j < 8; j++)
            #pragma unroll
            for (int q = 0; q < 4; q++) c[i][j][q] = 0.f;

    float4 ra[4], rb[4];

    auto ldg = [&](int ch) {
        int k0 = ch << 5;
        #pragma unroll
        for (int i = 0; i < 4; i++) {
            int idx = tid + (i << 8);
            ra[i] = *(const float4*)(A + (size_t)(m0 + (idx >> 3)) * K + k0 + ((idx & 7) << 2));
            if (NN)
                rb[i] = *(const float4*)(B + (size_t)(k0 + (idx >> 5)) * N + n0 + ((idx & 31) << 2));
            else
                rb[i] = *(const float4*)(B + (size_t)(n0 + (idx >> 3)) * K + k0 + ((idx & 7) << 2));
        }
    };
    auto sts = [&](int stg) {
        char* bs = sm + stg * 40960;
        #pragma unroll
        for (int i = 0; i < 4; i++) {
            int idx = tid + (i << 8);
            uint32_t h0, l0, h1, l1;
            cvtp(ra[i].x, ra[i].y, h0, l0);
            cvtp(ra[i].z, ra[i].w, h1, l1);
            {
                int row = idx >> 3, c4 = idx & 7;
                int off = row * 80 + c4 * 8;
                *(uint2*)(bs + off)         = make_uint2(h0, h1);
                *(uint2*)(bs + 10240 + off) = make_uint2(l0, l1);
            }
            cvtp(rb[i].x, rb[i].y, h0, l0);
            cvtp(rb[i].z, rb[i].w, h1, l1);
            if (NN) {
                int row = idx >> 5, cc = idx & 31;
                int off = row * 272 + cc * 8;
                *(uint2*)(bs + 20480 + off) = make_uint2(h0, h1);
                *(uint2*)(bs + 30720 + off) = make_uint2(l0, l1);
            } else {
                int row = idx >> 3, c4 = idx & 7;
                int off = row * 80 + c4 * 8;
                *(uint2*)(bs + 20480 + off) = make_uint2(h0, h1);
                *(uint2*)(bs + 30720 + off) = make_uint2(l0, l1);
            }
        }
    };

    // ldmatrix lane-address offsets (bytes from stage base)
    uint32_t aOff   = (uint32_t)((wm + (lane & 15)) * 80 + (lane >> 4) * 16);
    uint32_t bOffNT = (uint32_t)(20480 + (wn + (lane & 7) + ((lane >> 4) << 3)) * 80
                                 + ((lane >> 3) & 1) * 16);
    uint32_t bOffNN = (uint32_t)(20480 + ((lane & 7) + (((lane >> 3) & 1) << 3)) * 272
                                 + (wn + ((lane >> 4) << 3)) * 2);

    ldg(0); sts(0); __syncthreads();

    for (int ch = 0; ch < nch; ch++) {
        if (ch + 1 < nch) ldg(ch + 1);
        uint32_t base = sb + (uint32_t)(ch & 1) * 40960u;
        #pragma unroll
        for (int ks = 0; ks < 2; ks++) {
            uint32_t ah[2][4], al[2][4], bh[8][2], bl[8][2];
            #pragma unroll
            for (int mt = 0; mt < 2; mt++) {
                uint32_t ad = base + aOff + mt * 1280 + ks * 32;
                LDSM4(ah[mt][0], ah[mt][1], ah[mt][2], ah[mt][3], ad);
                LDSM4(al[mt][0], al[mt][1], al[mt][2], al[mt][3], ad + 10240);
            }
            #pragma unroll
            for (int p = 0; p < 4; p++) {
                if (NN) {
                    uint32_t bd = base + bOffNN + ks * 4352 + p * 32;
                    LDSM4T(bh[2*p][0], bh[2*p][1], bh[2*p+1][0], bh[2*p+1][1], bd);
                    LDSM4T(bl[2*p][0], bl[2*p][1], bl[2*p+1][0], bl[2*p+1][1], bd + 10240);
                } else {
                    uint32_t bd = base + bOffNT + p * 1280 + ks * 32;
                    LDSM4(bh[2*p][0], bh[2*p][1], bh[2*p+1][0], bh[2*p+1][1], bd);
                    LDSM4(bl[2*p][0], bl[2*p][1], bl[2*p+1][0], bl[2*p+1][1], bd + 10240);
                }
            }
            // 3-term split: hi*hi, hi*lo, lo*hi (16 independent MMAs per term)
            #pragma unroll
            for (int mt = 0; mt < 2; mt++)
                #pragma unroll
                for (int nt = 0; nt < 8; nt++)
                    MMA16816(c[mt][nt], ah[mt], bh[nt]);
            #pragma unroll
            for (int mt = 0; mt < 2; mt++)
                #pragma unroll
                for (int nt = 0; nt < 8; nt++)
                    MMA16816(c[mt][nt], ah[mt], bl[nt]);
            #pragma unroll
            for (int mt = 0; mt < 2; mt++)
                #pragma unroll
                for (int nt = 0; nt < 8; nt++)
                    MMA16816(c[mt][nt], al[mt], bh[nt]);
        }
        if (ch + 1 < nch) sts((ch + 1) & 1);
        __syncthreads();
    }

    // epilogue: direct float2 stores
    int g = lane >> 2, tg = lane & 3;
    #pragma unroll
    for (int mt = 0; mt < 2; mt++) {
        #pragma unroll
        for (int nt = 0; nt < 8; nt++) {
            int n = n0 + wn + nt * 8 + tg * 2;
            #pragma unroll
            for (int hr = 0; hr < 2; hr++) {
                int m = m0 + wm + mt * 16 + g + hr * 8;
                float v0 = c[mt][nt][hr * 2 + 0], v1 = c[mt][nt][hr * 2 + 1];
                if (bias) { v0 += __ldg(&bias[n]); v1 += __ldg(&bias[n + 1]); }
                if (res) {
                    float2 r = *(const float2*)(res + (size_t)m * N + n);
                    v0 += r.x; v1 += r.y;
                }
                if (RELU) { v0 = fmaxf(v0, 0.f); v1 = fmaxf(v1, 0.f); }
                *(float2*)(C + (size_t)m * N + n) = make_float2(v0, v1);
            }
        }
    }
}

// ---------------- LayerNorm ---------------------------------------------------
__global__ void ln_kernel(const float* __restrict__ x,
                          const float* __restrict__ gamma,
                          const float* __restrict__ beta,
                          float* __restrict__ out)
{
    int row = blockIdx.x;
    const float* xr = x + (size_t)row * Ee;
    float* orow = out + (size_t)row * Ee;
    float s = 0.f, s2 = 0.f;
    for (int i = threadIdx.x; i < Ee; i += 256) {
        float v = xr[i]; s += v; s2 += v * v;
    }
    __shared__ float sh[64];
    #pragma unroll
    for (int off = 16; off; off >>= 1) {
        s  += __shfl_xor_sync(0xffffffffu, s,  off);
        s2 += __shfl_xor_sync(0xffffffffu, s2, off);
    }
    int w = threadIdx.x >> 5, lane = threadIdx.x & 31;
    if (lane == 0) { sh[w] = s; sh[32 + w] = s2; }
    __syncthreads();
    if (w == 0) {
        s  = (lane < 8) ? sh[lane] : 0.f;
        s2 = (lane < 8) ? sh[32 + lane] : 0.f;
        #pragma unroll
        for (int off = 4; off; off >>= 1) {
            s  += __shfl_xor_sync(0xffffffffu, s,  off);
            s2 += __shfl_xor_sync(0xffffffffu, s2, off);
        }
        if (lane == 0) { sh[0] = s; sh[1] = s2; }
    }
    __syncthreads();
    float mean = sh[0] * (1.f / Ee);
    float var  = sh[1] * (1.f / Ee) - mean * mean;
    float inv  = rsqrtf(var + 1e-5f);
    for (int i = threadIdx.x; i < Ee; i += 256)
        orow[i] = (xr[i] - mean) * inv * gamma[i] + beta[i];
}

// ---------------- causal softmax ----------------------------------------------
__global__ void softmax_kernel(float* __restrict__ S)
{
    int t = blockIdx.x, b = blockIdx.y;
    float* row = S + ((size_t)b * Tt + t) * Tt;
    int n = t + 1;
    const float scale = 0.0220970869120796101f;  // 1/sqrt(2048)
    __shared__ float sh[32];
    int w = threadIdx.x >> 5, lane = threadIdx.x & 31;

    float mx = -3.4e38f;
    for (int i = threadIdx.x; i < n; i += 256) mx = fmaxf(mx, row[i]);
    #pragma unroll
    for (int off = 16; off; off >>= 1) mx = fmaxf(mx, __shfl_xor_sync(0xffffffffu, mx, off));
    if (lane == 0) sh[w] = mx;
    __syncthreads();
    if (w == 0) {
        mx = (lane < 8) ? sh[lane] : -3.4e38f;
        #pragma unroll
        for (int off = 4; off; off >>= 1) mx = fmaxf(mx, __shfl_xor_sync(0xffffffffu, mx, off));
        if (lane == 0) sh[0] = mx;
    }
    __syncthreads();
    mx = sh[0];
    __syncthreads();

    float sum = 0.f;
    for (int i = threadIdx.x; i < n; i += 256) sum += __expf((row[i] - mx) * scale);
    #pragma unroll
    for (int off = 16; off; off >>= 1) sum += __shfl_xor_sync(0xffffffffu, sum, off);
    if (lane == 0) sh[w] = sum;
    __syncthreads();
    if (w == 0) {
        sum = (lane < 8) ? sh[lane] : 0.f;
        #pragma unroll
        for (int off = 4; off; off >>= 1) sum += __shfl_xor_sync(0xffffffffu, sum, off);
        if (lane == 0) sh[0] = sum;
    }
    __syncthreads();
    float inv = 1.f / sh[0];
    for (int i = threadIdx.x; i < Tt; i += 256)
        row[i] = (i < n) ? __expf((row[i] - mx) * scale) * inv : 0.f;
}

// ---------------- launch -------------------------------------------------------
extern "C" void kernel_launch(void* const* d_in, const int* in_sizes, int n_in,
                              void* d_out, int out_size)
{
    const float* x      = (const float*)d_in[0];
    const float* gamma1 = (const float*)d_in[1];
    const float* beta1  = (const float*)d_in[2];
    const float* Wq     = (const float*)d_in[3];
    const float* Wk     = (const float*)d_in[4];
    const float* Wv     = (const float*)d_in[5];
    const float* Wo     = (const float*)d_in[6];
    const float* bo     = (const float*)d_in[7];
    const float* gamma2 = (const float*)d_in[8];
    const float* beta2  = (const float*)d_in[9];
    const float* W1     = (const float*)d_in[10];
    const float* b1     = (const float*)d_in[11];
    const float* W2     = (const float*)d_in[12];
    const float* b2     = (const float*)d_in[13];
    float* out = (float*)d_out;

    float *h, *q, *k, *v, *s, *attn, *x1, *ff;
    cudaGetSymbolAddress((void**)&h,    g_h);
    cudaGetSymbolAddress((void**)&q,    g_q);
    cudaGetSymbolAddress((void**)&k,    g_k);
    cudaGetSymbolAddress((void**)&v,    g_v);
    cudaGetSymbolAddress((void**)&s,    g_s);
    cudaGetSymbolAddress((void**)&attn, g_attn);
    cudaGetSymbolAddress((void**)&x1,   g_x1);
    cudaGetSymbolAddress((void**)&ff,   g_ff);

    cudaFuncSetAttribute(hgemm<false, false>, cudaFuncAttributeMaxDynamicSharedMemorySize, HSMEM);
    cudaFuncSetAttribute(hgemm<false, true>,  cudaFuncAttributeMaxDynamicSharedMemorySize, HSMEM);
    cudaFuncSetAttribute(hgemm<true,  false>, cudaFuncAttributeMaxDynamicSharedMemorySize, HSMEM);

    // 1) LN1
    ln_kernel<<<MR, 256>>>(x, gamma1, beta1, h);

    // 2) Q, K, V projections (NT)
    dim3 gProj(Ee / 128, MR / 128, 1);
    hgemm<false, false><<<gProj, 256, HSMEM>>>(h, Wq, nullptr, nullptr, q, Ee, Ee, 0, 0, 0, 0);
    hgemm<false, false><<<gProj, 256, HSMEM>>>(h, Wk, nullptr, nullptr, k, Ee, Ee, 0, 0, 0, 0);
    hgemm<false, false><<<gProj, 256, HSMEM>>>(h, Wv, nullptr, nullptr, v, Ee, Ee, 0, 0, 0, 0);

    // 3) S = q k^T (batched, causal tile skip)
    dim3 gQK(Tt / 128, Tt / 128, Bb);
    hgemm<false, false><<<gQK, 256, HSMEM>>>(q, k, nullptr, nullptr, s, Tt, Ee,
                                             (size_t)Tt * Ee, (size_t)Tt * Ee, (size_t)Tt * Tt, 1);

    // 4) causal softmax
    softmax_kernel<<<dim3(Tt, Bb), 256>>>(s);

    // 5) attn = S @ V (NN, K clamped at diagonal)
    dim3 gPV(Ee / 128, Tt / 128, Bb);
    hgemm<true, false><<<gPV, 256, HSMEM>>>(s, v, nullptr, nullptr, attn, Ee, Tt,
                                            (size_t)Tt * Tt, (size_t)Tt * Ee, (size_t)Tt * Ee, 2);

    // 6) x1 = attn Wo^T + bo + x
    hgemm<false, false><<<gProj, 256, HSMEM>>>(attn, Wo, bo, x, x1, Ee, Ee, 0, 0, 0, 0);

    // 7) LN2
    ln_kernel<<<MR, 256>>>(x1, gamma2, beta2, h);

    // 8) ff = relu(h W1^T + b1)
    dim3 gFF1(FFF / 128, MR / 128, 1);
    hgemm<false, true><<<gFF1, 256, HSMEM>>>(h, W1, b1, nullptr, ff, FFF, Ee, 0, 0, 0, 0);

    // 9) out = ff W2^T + b2 + x1
    dim3 gFF2(Ee / 128, MR / 128, 1);
    hgemm<false, false><<<gFF2, 256, HSMEM>>>(ff, W2, b2, x1, out, Ee, FFF, 0, 0, 0, 0);
}